// round 12
// baseline (speedup 1.0000x reference)
#include <cuda_runtime.h>

#define B_   4
#define N_   4096
#define K_   512
#define NT   32                 // children per CTA
#define GRID_X (N_/NT)          // 128
#define GRID_TOTAL (GRID_X*B_)  // 512
#define NTHR 256                // thread owns parents 2*tid, 2*tid+1 (f32x2 lanes)
#define ROWB (K_*4)             // 2048 B per A row
#define ABYTES (NT*ROWB)        // 65536
#define SH_A    0
#define SH_F    ABYTES                  // 65536
#define SH_REDP (SH_F + NT*80)          // 68096
#define SH_REDC (SH_REDP + 32)
#define SH_MASK (SH_REDC + 32)
#define SH_LAST (SH_MASK + 4)
#define SH_MBAR (SH_LAST + 4)
#define SMEM_TOTAL (SH_MBAR + 16)
#define EPSF 1e-6f

typedef unsigned long long ull;

__device__ double   g_blkP[GRID_TOTAL];
__device__ double   g_blkC[GRID_TOTAL];
__device__ float    g_blkM[GRID_TOTAL];
__device__ unsigned g_cnt;   // zero-init; atomicInc wrap resets each launch

__device__ __forceinline__ ull pack2(float lo, float hi) {
    ull r; asm("mov.b64 %0, {%1, %2};" : "=l"(r) : "f"(lo), "f"(hi)); return r;
}
__device__ __forceinline__ float2 unpack2(ull v) {
    float2 r; asm("mov.b64 {%0, %1}, %2;" : "=f"(r.x), "=f"(r.y) : "l"(v)); return r;
}
__device__ __forceinline__ ull fma2(ull a, ull b, ull c) {
    ull d; asm("fma.rn.f32x2 %0, %1, %2, %3;" : "=l"(d) : "l"(a), "l"(b), "l"(c)); return d;
}
__device__ __forceinline__ ull mul2(ull a, ull b) {
    ull d; asm("mul.rn.f32x2 %0, %1, %2;" : "=l"(d) : "l"(a), "l"(b)); return d;
}
__device__ __forceinline__ ull add2(ull a, ull b) {
    ull d; asm("add.rn.f32x2 %0, %1, %2;" : "=l"(d) : "l"(a), "l"(b)); return d;
}
__device__ __forceinline__ void lds2(unsigned addr, ull& x, ull& y) {
    asm("ld.shared.v2.b64 {%0, %1}, [%2];" : "=l"(x), "=l"(y) : "r"(addr));
}
__device__ __forceinline__ ull lds64(unsigned addr) {
    ull v; asm("ld.shared.b64 %0, [%1];" : "=l"(v) : "r"(addr)); return v;
}
__device__ __forceinline__ void mbar_init(unsigned addr, unsigned cnt) {
    asm volatile("mbarrier.init.shared.b64 [%0], %1;" :: "r"(addr), "r"(cnt) : "memory");
}
__device__ __forceinline__ void mbar_expect_tx(unsigned addr, unsigned bytes) {
    asm volatile("mbarrier.arrive.expect_tx.shared.b64 _, [%0], %1;"
                 :: "r"(addr), "r"(bytes) : "memory");
}
__device__ __forceinline__ void bulk_g2s(unsigned sdst, const void* gsrc,
                                         unsigned bytes, unsigned mbar) {
    asm volatile("cp.async.bulk.shared::cluster.global.mbarrier::complete_tx::bytes "
                 "[%0], [%1], %2, [%3];"
                 :: "r"(sdst), "l"(gsrc), "r"(bytes), "r"(mbar) : "memory");
}
__device__ __forceinline__ void mbar_wait(unsigned addr, unsigned parity) {
    unsigned done;
    asm volatile(
        "{\n\t.reg .pred p;\n\t"
        "mbarrier.try_wait.parity.acquire.cta.shared::cta.b64 p, [%1], %2;\n\t"
        "selp.b32 %0, 1, 0, p;\n\t}"
        : "=r"(done) : "r"(addr), "r"(parity) : "memory");
    if (!done) {
        asm volatile(
            "{\n\t.reg .pred P1;\n\t"
            "WL_%=:\n\t"
            "mbarrier.try_wait.parity.acquire.cta.shared::cta.b64 P1, [%0], %1, 0x989680;\n\t"
            "@P1 bra.uni WD_%=;\n\t"
            "bra.uni WL_%=;\n\t"
            "WD_%=:\n\t}"
            :: "r"(addr), "r"(parity) : "memory");
    }
}

// symmetric 3x3 inverse of (S + eps*I)
__device__ __forceinline__ void inv3sym(const float* __restrict__ S,
                                        float& i00, float& i01, float& i02,
                                        float& i11, float& i12, float& i22) {
    float s00 = S[0] + EPSF, s01 = S[1], s02 = S[2];
    float s11 = S[4] + EPSF, s12 = S[5];
    float s22 = S[8] + EPSF;
    float c00 = s11 * s22 - s12 * s12;
    float c01 = s02 * s12 - s01 * s22;
    float c02 = s01 * s12 - s02 * s11;
    float c11 = s00 * s22 - s02 * s02;
    float c12 = s01 * s02 - s00 * s12;
    float c22 = s00 * s11 - s01 * s01;
    float det = s00 * c00 + s01 * c01 + s02 * c02;
    float id  = 1.0f / det;
    i00 = c00 * id; i01 = c01 * id; i02 = c02 * id;
    i11 = c11 * id; i12 = c12 * id; i22 = c22 * id;
}

__global__ void __launch_bounds__(NTHR, 3)
loss_kernel(const float* __restrict__ muC, const float* __restrict__ SC,
            const float* __restrict__ muP, const float* __restrict__ SP,
            const float* __restrict__ A,   const float* __restrict__ mask,
            float* __restrict__ out)
{
    extern __shared__ __align__(128) char smem[];
    float* shF   = (float*)(smem + SH_F);
    float* redP  = (float*)(smem + SH_REDP);
    float* redC  = (float*)(smem + SH_REDC);
    float* sMask = (float*)(smem + SH_MASK);
    int*   sLast = (int*)  (smem + SH_LAST);

    const int b   = blockIdx.y;
    const int n0  = blockIdx.x * NT;
    const int tid = threadIdx.x;
    const int k0  = 2 * tid;
    unsigned sbase = (unsigned)__cvta_generic_to_shared(smem);

    // ---- kick off ONE TMA bulk load of the whole 64KB A block ----
    if (tid == 0) {
        mbar_init(sbase + SH_MBAR, 1);
        asm volatile("fence.proxy.async.shared::cta;" ::: "memory");
        const char* gA = (const char*)(A + ((size_t)b * N_ + n0) * K_);
        mbar_expect_tx(sbase + SH_MBAR, ABYTES);
        bulk_g2s(sbase + SH_A, gA, ABYTES, sbase + SH_MBAR);
    }

    // ---- parent-pair features, packed {k0, k1} (overlaps TMA) ----
    float a00, a01, a02, a11, a12, a22;
    float b00, b01, b02, b11, b12, b22;
    inv3sym(SP + (size_t)(b * K_ + k0) * 9,     a00, a01, a02, a11, a12, a22);
    inv3sym(SP + (size_t)(b * K_ + k0 + 1) * 9, b00, b01, b02, b11, b12, b22);
    const float* mpA = muP + (size_t)(b * K_ + k0) * 3;
    const float* mpB = muP + (size_t)(b * K_ + k0 + 1) * 3;
    ull Pn0  = pack2(-mpA[0], -mpB[0]);
    ull Pn1  = pack2(-mpA[1], -mpB[1]);
    ull Pn2  = pack2(-mpA[2], -mpB[2]);
    ull PI00 = pack2(a00, b00);
    ull PI11 = pack2(a11, b11);
    ull PI22 = pack2(a22, b22);
    ull PI01 = pack2(2.f * a01, 2.f * b01);
    ull PI02 = pack2(2.f * a02, 2.f * b02);
    ull PI12 = pack2(2.f * a12, 2.f * b12);

    // ---- child features -> shared, duplicated {v,v} (overlaps TMA) ----
    if (tid < NT) {
        int n = n0 + tid;
        float j00, j01, j02, j11, j12, j22;
        inv3sym(SC + (size_t)(b * N_ + n) * 9, j00, j01, j02, j11, j12, j22);
        const float* mc = muC + (size_t)(b * N_ + n) * 3;
        float m = mask[b * N_ + n];
        float* d = &shF[tid * 20];
        d[0]  = mc[0];      d[1]  = mc[0];
        d[2]  = mc[1];      d[3]  = mc[1];
        d[4]  = mc[2];      d[5]  = mc[2];
        d[6]  = j00;        d[7]  = j00;
        d[8]  = j11;        d[9]  = j11;
        d[10] = j22;        d[11] = j22;
        d[12] = 2.f * j01;  d[13] = 2.f * j01;
        d[14] = 2.f * j02;  d[15] = 2.f * j02;
        d[16] = 2.f * j12;  d[17] = 2.f * j12;
        d[18] = m;          d[19] = m;
    }
    __syncthreads();

    // block mask partial: warp 0, lane i owns child i
    if (tid < 32) {
        float m = shF[tid * 20 + 18];
#pragma unroll
        for (int off = 16; off; off >>= 1)
            m += __shfl_down_sync(0xffffffffu, m, off);
        if (tid == 0) *sMask = m;
    }

    // ---- single wait: whole A tile resident; loop below is branch-free ----
    mbar_wait(sbase + SH_MBAR, 0);

    unsigned fbase = sbase + SH_F;
    unsigned abase = sbase + SH_A + tid * 8;

    ull accP = 0ull, accC = 0ull;

#pragma unroll
    for (int n = 0; n < NT; ++n) {
        ull araw = lds64(abase + n * ROWB);   // {A(n,k0), A(n,k1)} packed

        unsigned ad = fbase + n * 80;
        ull Fc0, Fc1, Fc2, FJ00, FJ11, FJ22, FJ01, FJ02, FJ12, Fm;
        lds2(ad,      Fc0,  Fc1 );
        lds2(ad + 16, Fc2,  FJ00);
        lds2(ad + 32, FJ11, FJ22);
        lds2(ad + 48, FJ01, FJ02);
        lds2(ad + 64, FJ12, Fm  );

        ull d0 = add2(Fc0, Pn0);
        ull d1 = add2(Fc1, Pn1);
        ull d2 = add2(Fc2, Pn2);

        ull dd, mp, mc;
        dd = mul2(d0, d0);
        mp = mul2(dd, PI00);      mc = mul2(dd, FJ00);
        dd = mul2(d1, d1);
        mp = fma2(dd, PI11, mp);  mc = fma2(dd, FJ11, mc);
        dd = mul2(d2, d2);
        mp = fma2(dd, PI22, mp);  mc = fma2(dd, FJ22, mc);
        dd = mul2(d0, d1);
        mp = fma2(dd, PI01, mp);  mc = fma2(dd, FJ01, mc);
        dd = mul2(d0, d2);
        mp = fma2(dd, PI02, mp);  mc = fma2(dd, FJ02, mc);
        dd = mul2(d1, d2);
        mp = fma2(dd, PI12, mp);  mc = fma2(dd, FJ12, mc);

        ull am = mul2(araw, Fm);   // {A,A} * mask
        accP = fma2(am, mp, accP);
        accC = fma2(am, mc, accC);
    }

    // ---- in-block reduction ----
    float2 vP = unpack2(accP), vC = unpack2(accC);
    float sp = vP.x + vP.y;
    float sc = vC.x + vC.y;
#pragma unroll
    for (int off = 16; off; off >>= 1) {
        sp += __shfl_down_sync(0xffffffffu, sp, off);
        sc += __shfl_down_sync(0xffffffffu, sc, off);
    }
    int wid = tid >> 5, lane = tid & 31;
    if (lane == 0) { redP[wid] = sp; redC[wid] = sc; }
    __syncthreads();

    const int bid = blockIdx.y * gridDim.x + blockIdx.x;
    if (tid == 0) {
        float tp = 0.f, tc = 0.f;
#pragma unroll
        for (int i = 0; i < 8; i++) { tp += redP[i]; tc += redC[i]; }
        g_blkP[bid] = (double)tp;
        g_blkC[bid] = (double)tc;
        g_blkM[bid] = *sMask;
        __threadfence();
        unsigned t = atomicInc(&g_cnt, GRID_TOTAL - 1);
        *sLast = (t == GRID_TOTAL - 1);
    }
    __syncthreads();

    // ---- last block: final reduction + output ----
    if (*sLast) {
        __threadfence();
        __shared__ double fP[8], fC[8];
        __shared__ float  fM[8];
        double p = g_blkP[tid] + g_blkP[tid + NTHR];   // 512 slots
        double c = g_blkC[tid] + g_blkC[tid + NTHR];
        float  m = g_blkM[tid] + g_blkM[tid + NTHR];
#pragma unroll
        for (int off = 16; off; off >>= 1) {
            p += __shfl_down_sync(0xffffffffu, p, off);
            c += __shfl_down_sync(0xffffffffu, c, off);
            m += __shfl_down_sync(0xffffffffu, m, off);
        }
        if (lane == 0) { fP[wid] = p; fC[wid] = c; fM[wid] = m; }
        __syncthreads();
        if (tid == 0) {
            double tp = 0.0, tc = 0.0;
            float  tm = 0.f;
#pragma unroll
            for (int i = 0; i < 8; i++) { tp += fP[i]; tc += fC[i]; tm += fM[i]; }
            double denom = (tm > 1.f) ? (double)tm : 1.0;
            out[0] = (float)((tp + tc) / denom);  // final_loss
            out[1] = (float)(tp / denom);          // dist_p_m
            out[2] = (float)(tc / denom);          // dist_c_m
        }
    }
}

extern "C" void kernel_launch(void* const* d_in, const int* in_sizes, int n_in,
                              void* d_out, int out_size) {
    const float* muC  = (const float*)d_in[0];
    const float* SC   = (const float*)d_in[1];
    const float* muP  = (const float*)d_in[2];
    const float* SP   = (const float*)d_in[3];
    const float* A    = (const float*)d_in[4];
    const float* mask = (const float*)d_in[5];

    cudaFuncSetAttribute(loss_kernel,
                         cudaFuncAttributeMaxDynamicSharedMemorySize, SMEM_TOTAL);
    dim3 grid(GRID_X, B_);
    loss_kernel<<<grid, NTHR, SMEM_TOTAL>>>(muC, SC, muP, SP, A, mask, (float*)d_out);
}

// round 13
// speedup vs baseline: 1.0952x; 1.0952x over previous
#include <cuda_runtime.h>

#define B_   4
#define N_   4096
#define K_   512
#define NT   64                 // children per CTA
#define NSUPER (NT/2)           // 32 super-iterations (2 children each)
#define GRID_X (N_/NT)          // 64
#define GRID_TOTAL (GRID_X*B_)  // 256
#define NTHR 256                // thread owns parents 2*tid, 2*tid+1 (f32x2 lanes)
#define DEPTH 4                 // prefetch depth in super-iters (8 rows ahead)
#define EPSF 1e-6f

typedef unsigned long long ull;

__device__ double   g_blkP[GRID_TOTAL];
__device__ double   g_blkC[GRID_TOTAL];
__device__ float    g_blkM[GRID_TOTAL];
__device__ unsigned g_cnt;   // zero-init; atomicInc wrap resets each launch

__device__ __forceinline__ ull pack2(float lo, float hi) {
    ull r; asm("mov.b64 %0, {%1, %2};" : "=l"(r) : "f"(lo), "f"(hi)); return r;
}
__device__ __forceinline__ float2 unpack2(ull v) {
    float2 r; asm("mov.b64 {%0, %1}, %2;" : "=f"(r.x), "=f"(r.y) : "l"(v)); return r;
}
__device__ __forceinline__ ull fma2(ull a, ull b, ull c) {
    ull d; asm("fma.rn.f32x2 %0, %1, %2, %3;" : "=l"(d) : "l"(a), "l"(b), "l"(c)); return d;
}
__device__ __forceinline__ ull mul2(ull a, ull b) {
    ull d; asm("mul.rn.f32x2 %0, %1, %2;" : "=l"(d) : "l"(a), "l"(b)); return d;
}
__device__ __forceinline__ ull add2(ull a, ull b) {
    ull d; asm("add.rn.f32x2 %0, %1, %2;" : "=l"(d) : "l"(a), "l"(b)); return d;
}
__device__ __forceinline__ void lds2(unsigned addr, ull& x, ull& y) {
    asm("ld.shared.v2.b64 {%0, %1}, [%2];" : "=l"(x), "=l"(y) : "r"(addr));
}

// symmetric 3x3 inverse of (S + eps*I)
__device__ __forceinline__ void inv3sym(const float* __restrict__ S,
                                        float& i00, float& i01, float& i02,
                                        float& i11, float& i12, float& i22) {
    float s00 = S[0] + EPSF, s01 = S[1], s02 = S[2];
    float s11 = S[4] + EPSF, s12 = S[5];
    float s22 = S[8] + EPSF;
    float c00 = s11 * s22 - s12 * s12;
    float c01 = s02 * s12 - s01 * s22;
    float c02 = s01 * s12 - s02 * s11;
    float c11 = s00 * s22 - s02 * s02;
    float c12 = s01 * s02 - s00 * s12;
    float c22 = s00 * s11 - s01 * s01;
    float det = s00 * c00 + s01 * c01 + s02 * c02;
    float id  = 1.0f / det;
    i00 = c00 * id; i01 = c01 * id; i02 = c02 * id;
    i11 = c11 * id; i12 = c12 * id; i22 = c22 * id;
}

__global__ void __launch_bounds__(NTHR, 2)
loss_kernel(const float* __restrict__ muC, const float* __restrict__ SC,
            const float* __restrict__ muP, const float* __restrict__ SP,
            const float* __restrict__ A,   const float* __restrict__ mask,
            float* __restrict__ out)
{
    // per child n: 10 features, each DUPLICATED {v,v} -> 80B:
    // c0,c1,c2, J00,J11,J22, 2J01,2J02,2J12, m
    __shared__ float shF[NT * 20];
    __shared__ float redP[8], redC[8];
    __shared__ float sMask;
    __shared__ int   sLast;

    const int b   = blockIdx.y;
    const int n0  = blockIdx.x * NT;
    const int tid = threadIdx.x;
    const int k0  = 2 * tid;

    // ---- parent-pair features, packed {k0, k1} (9 ull = 18 regs) ----
    float a00, a01, a02, a11, a12, a22;
    float b00, b01, b02, b11, b12, b22;
    inv3sym(SP + (size_t)(b * K_ + k0) * 9,     a00, a01, a02, a11, a12, a22);
    inv3sym(SP + (size_t)(b * K_ + k0 + 1) * 9, b00, b01, b02, b11, b12, b22);
    const float* mpA = muP + (size_t)(b * K_ + k0) * 3;
    const float* mpB = muP + (size_t)(b * K_ + k0 + 1) * 3;
    ull Pn0  = pack2(-mpA[0], -mpB[0]);
    ull Pn1  = pack2(-mpA[1], -mpB[1]);
    ull Pn2  = pack2(-mpA[2], -mpB[2]);
    ull PI00 = pack2(a00, b00);
    ull PI11 = pack2(a11, b11);
    ull PI22 = pack2(a22, b22);
    ull PI01 = pack2(2.f * a01, 2.f * b01);
    ull PI02 = pack2(2.f * a02, 2.f * b02);
    ull PI12 = pack2(2.f * a12, 2.f * b12);

    // ---- child features -> shared, duplicated {v,v} ----
    if (tid < NT) {
        int n = n0 + tid;
        float j00, j01, j02, j11, j12, j22;
        inv3sym(SC + (size_t)(b * N_ + n) * 9, j00, j01, j02, j11, j12, j22);
        const float* mc = muC + (size_t)(b * N_ + n) * 3;
        float m = mask[b * N_ + n];
        float* d = &shF[tid * 20];
        d[0]  = mc[0];      d[1]  = mc[0];
        d[2]  = mc[1];      d[3]  = mc[1];
        d[4]  = mc[2];      d[5]  = mc[2];
        d[6]  = j00;        d[7]  = j00;
        d[8]  = j11;        d[9]  = j11;
        d[10] = j22;        d[11] = j22;
        d[12] = 2.f * j01;  d[13] = 2.f * j01;
        d[14] = 2.f * j02;  d[15] = 2.f * j02;
        d[16] = 2.f * j12;  d[17] = 2.f * j12;
        d[18] = m;          d[19] = m;
    }
    __syncthreads();

    // block mask partial: warp 0, lane i owns children i and i+32
    if (tid < 32) {
        float m = shF[tid * 20 + 18] + shF[(tid + 32) * 20 + 18];
#pragma unroll
        for (int off = 16; off; off >>= 1)
            m += __shfl_down_sync(0xffffffffu, m, off);
        if (tid == 0) sMask = m;
    }

    unsigned fbase = (unsigned)__cvta_generic_to_shared(shF);
    // A row n, parents (k0, k0+1) adjacent: one float2 per child row
    const float2* Ap = (const float2*)(A + ((size_t)b * N_ + n0) * K_) + tid;

    // prefetch 2*DEPTH = 8 rows
    float2 abuf[2 * DEPTH];
#pragma unroll
    for (int i = 0; i < DEPTH; i++) {
        abuf[2 * i]     = __ldcs(Ap);
        abuf[2 * i + 1] = __ldcs(Ap + K_ / 2);
        Ap += K_;
    }

    ull accP = 0ull, accC = 0ull;

#pragma unroll
    for (int p = 0; p < NSUPER; ++p) {
        int s = (p & (DEPTH - 1)) * 2;
        float2 av0 = abuf[s];        // child 2p
        float2 av1 = abuf[s + 1];    // child 2p+1
        if (p < NSUPER - DEPTH) {
            abuf[s]     = __ldcs(Ap);
            abuf[s + 1] = __ldcs(Ap + K_ / 2);
            Ap += K_;
        }

        // ---- two independent children, interleaved in one basic block ----
        unsigned adA = fbase + (2 * p) * 80;
        unsigned adB = adA + 80;
        ull Ac0, Ac1, Ac2, AJ00, AJ11, AJ22, AJ01, AJ02, AJ12, Am_;
        ull Bc0, Bc1, Bc2, BJ00, BJ11, BJ22, BJ01, BJ02, BJ12, Bm_;
        lds2(adA,      Ac0,  Ac1 );
        lds2(adB,      Bc0,  Bc1 );
        lds2(adA + 16, Ac2,  AJ00);
        lds2(adB + 16, Bc2,  BJ00);
        lds2(adA + 32, AJ11, AJ22);
        lds2(adB + 32, BJ11, BJ22);
        lds2(adA + 48, AJ01, AJ02);
        lds2(adB + 48, BJ01, BJ02);
        lds2(adA + 64, AJ12, Am_ );
        lds2(adB + 64, BJ12, Bm_ );

        ull da0 = add2(Ac0, Pn0);
        ull db0 = add2(Bc0, Pn0);
        ull da1 = add2(Ac1, Pn1);
        ull db1 = add2(Bc1, Pn1);
        ull da2 = add2(Ac2, Pn2);
        ull db2 = add2(Bc2, Pn2);

        ull ta, tb, mpa, mpb, mca, mcb;
        ta = mul2(da0, da0);            tb = mul2(db0, db0);
        mpa = mul2(ta, PI00);           mpb = mul2(tb, PI00);
        mca = mul2(ta, AJ00);           mcb = mul2(tb, BJ00);
        ta = mul2(da1, da1);            tb = mul2(db1, db1);
        mpa = fma2(ta, PI11, mpa);      mpb = fma2(tb, PI11, mpb);
        mca = fma2(ta, AJ11, mca);      mcb = fma2(tb, BJ11, mcb);
        ta = mul2(da2, da2);            tb = mul2(db2, db2);
        mpa = fma2(ta, PI22, mpa);      mpb = fma2(tb, PI22, mpb);
        mca = fma2(ta, AJ22, mca);      mcb = fma2(tb, BJ22, mcb);
        ta = mul2(da0, da1);            tb = mul2(db0, db1);
        mpa = fma2(ta, PI01, mpa);      mpb = fma2(tb, PI01, mpb);
        mca = fma2(ta, AJ01, mca);      mcb = fma2(tb, BJ01, mcb);
        ta = mul2(da0, da2);            tb = mul2(db0, db2);
        mpa = fma2(ta, PI02, mpa);      mpb = fma2(tb, PI02, mpb);
        mca = fma2(ta, AJ02, mca);      mcb = fma2(tb, BJ02, mcb);
        ta = mul2(da1, da2);            tb = mul2(db1, db2);
        mpa = fma2(ta, PI12, mpa);      mpb = fma2(tb, PI12, mpb);
        mca = fma2(ta, AJ12, mca);      mcb = fma2(tb, BJ12, mcb);

        ull amA = mul2(pack2(av0.x, av0.y), Am_);
        ull amB = mul2(pack2(av1.x, av1.y), Bm_);
        accP = fma2(amA, mpa, accP);
        accC = fma2(amA, mca, accC);
        accP = fma2(amB, mpb, accP);
        accC = fma2(amB, mcb, accC);
    }

    // ---- in-block reduction ----
    float2 vP = unpack2(accP), vC = unpack2(accC);
    float sp = vP.x + vP.y;
    float sc = vC.x + vC.y;
#pragma unroll
    for (int off = 16; off; off >>= 1) {
        sp += __shfl_down_sync(0xffffffffu, sp, off);
        sc += __shfl_down_sync(0xffffffffu, sc, off);
    }
    int wid = tid >> 5, lane = tid & 31;
    if (lane == 0) { redP[wid] = sp; redC[wid] = sc; }
    __syncthreads();

    const int bid = blockIdx.y * gridDim.x + blockIdx.x;
    if (tid == 0) {
        float tp = 0.f, tc = 0.f;
#pragma unroll
        for (int i = 0; i < 8; i++) { tp += redP[i]; tc += redC[i]; }
        g_blkP[bid] = (double)tp;
        g_blkC[bid] = (double)tc;
        g_blkM[bid] = sMask;
        __threadfence();
        unsigned t = atomicInc(&g_cnt, GRID_TOTAL - 1);
        sLast = (t == GRID_TOTAL - 1);
    }
    __syncthreads();

    // ---- last block: final reduction + output ----
    if (sLast) {
        __threadfence();
        __shared__ double fP[8], fC[8];
        __shared__ float  fM[8];
        double p = g_blkP[tid];   // 256 slots, 256 threads
        double c = g_blkC[tid];
        float  m = g_blkM[tid];
#pragma unroll
        for (int off = 16; off; off >>= 1) {
            p += __shfl_down_sync(0xffffffffu, p, off);
            c += __shfl_down_sync(0xffffffffu, c, off);
            m += __shfl_down_sync(0xffffffffu, m, off);
        }
        if (lane == 0) { fP[wid] = p; fC[wid] = c; fM[wid] = m; }
        __syncthreads();
        if (tid == 0) {
            double tp = 0.0, tc = 0.0;
            float  tm = 0.f;
#pragma unroll
            for (int i = 0; i < 8; i++) { tp += fP[i]; tc += fC[i]; tm += fM[i]; }
            double denom = (tm > 1.f) ? (double)tm : 1.0;
            out[0] = (float)((tp + tc) / denom);  // final_loss
            out[1] = (float)(tp / denom);          // dist_p_m
            out[2] = (float)(tc / denom);          // dist_c_m
        }
    }
}

extern "C" void kernel_launch(void* const* d_in, const int* in_sizes, int n_in,
                              void* d_out, int out_size) {
    const float* muC  = (const float*)d_in[0];
    const float* SC   = (const float*)d_in[1];
    const float* muP  = (const float*)d_in[2];
    const float* SP   = (const float*)d_in[3];
    const float* A    = (const float*)d_in[4];
    const float* mask = (const float*)d_in[5];

    dim3 grid(GRID_X, B_);
    loss_kernel<<<grid, NTHR>>>(muC, SC, muP, SP, A, mask, (float*)d_out);
}